// round 2
// baseline (speedup 1.0000x reference)
#include <cuda_runtime.h>
#include <math.h>

// ---------------- problem constants ----------------
#define BATCH 16
#define CW    32          // width (channels)
#define HP    265         // padded H = W = 256 + 9
#define NPIX  70225       // 265*265
#define NK    13          // kept kx modes 0..12
#define NY    25          // kept ky modes -12..12
#define NPOS  325         // 25*13
#define NL    4
#define DCPOS 156         // (ky=0 -> y=12)*13 + 0
#define NF    70225.0f
#define INV_N (1.0f/70225.0f)

// ---------------- scratch (device globals; no allocation allowed) ----------------
__device__ float  g_x[(size_t)BATCH*CW*NPIX];        // main activation buffer, [b][c][h][w]
__device__ float2 g_F[(size_t)BATCH*CW*HP*NK];       // forward T1 / inverse G, [bc][h][kx]
__device__ float2 g_S[(size_t)BATCH*CW*NPOS];        // extracted modes (raw, pre-norm)
__device__ float2 g_Z[(size_t)BATCH*CW*NPOS];        // mixed modes
__device__ float  g_Wf[(size_t)NL*NPOS*CW*CW];       // built spectral weights, [l][pos][i][o]
__device__ float2 g_tw[HP];                          // e^{-2*pi*i*n/265}
__device__ float2 g_rowstats[(size_t)BATCH*CW*HP];   // per-row (sum, sumsq) of x
__device__ float  g_xsum[BATCH*CW], g_xsq[BATCH*CW];
__device__ float  g_ymu[BATCH*CW], g_yisig[BATCH*CW];

// ---------------- constant weights ----------------
__constant__ float c_pw[32], c_pb[32];
__constant__ float c_m1w[NL*1024], c_m1b[NL*32];
__constant__ float c_m2w[NL*1024], c_m2b[NL*32];
__constant__ float c_q1w[128*32], c_q1b[128];
__constant__ float c_q2w[128], c_q2b[1];

__device__ __forceinline__ float gelu(float v) {
    return 0.5f * v * (1.0f + erff(v * 0.7071067811865476f));
}

// ---------------- twiddle table (double precision init) ----------------
__global__ void k_tw() {
    int n = threadIdx.x;
    if (n < HP) {
        double a = -2.0 * 3.14159265358979323846 * (double)n / 265.0;
        g_tw[n] = make_float2((float)cos(a), (float)sin(a));
    }
}

// ---------------- build Wfull from W_LC / W_LR ----------------
// W_LC: [L,32,32,13,1], W_LR: [L,32,32,12,12]; output g_Wf[l][pos=y*13+x][i][o]
__global__ void k_buildW(const float* __restrict__ LC, const float* __restrict__ LR) {
    int idx = blockIdx.x * blockDim.x + threadIdx.x;
    if (idx >= NL * NPOS * 32 * 32) return;
    int o = idx & 31;
    int i = (idx >> 5) & 31;
    int pos = (idx >> 10) % NPOS;
    int l = idx / (NPOS * 1024);
    int y = pos / 13, x = pos % 13;
    int base = (l * 32 + i) * 32 + o;
    float v;
    if (y < 13) {
        if (x == 0) {
            v = LC[base * 13 + (12 - y)];
        } else {
            int r = x - 1, c = 12 - y;              // W_LRc[r][c]
            v = (c == 0) ? LC[base * 13 + (r + 1)]
                         : LR[(base * 12 + r) * 12 + (c - 1)];
        }
    } else {
        int r = y - 13;
        v = (x == 0) ? LC[base * 13 + (r + 1)]
                     : LR[(base * 12 + r) * 12 + (x - 1)];
    }
    g_Wf[idx] = v;
}

// ---------------- lift: conv1x1 (1->32) + zero pad to 265x265 ----------------
__global__ void k_lift(const float* __restrict__ xin) {
    size_t idx = (size_t)blockIdx.x * blockDim.x + threadIdx.x;
    if (idx >= (size_t)BATCH * CW * NPIX) return;
    int w = (int)(idx % HP);
    int h = (int)((idx / HP) % HP);
    int o = (int)((idx / NPIX) % CW);
    int b = (int)(idx / ((size_t)NPIX * CW));
    float v = 0.f;
    if (h < 256 && w < 256)
        v = c_pw[o] * xin[((size_t)b * 256 + h) * 256 + w] + c_pb[o];
    g_x[idx] = v;
}

// ---------------- stage A: forward DFT along w (265 -> 13) + per-row stats ----------------
__global__ void kA() {
    __shared__ float2 stw[HP];
    int tid = threadIdx.x;
    for (int j = tid; j < HP; j += 256) stw[j] = g_tw[j];
    __syncthreads();
    int warp = tid >> 5, lane = tid & 31;
    int h = blockIdx.y * 8 + warp;
    int bc = blockIdx.x;
    if (h >= HP) return;
    const float* row = g_x + ((size_t)bc * HP + h) * HP;
    float ar[NK], ai[NK];
    int m[NK], s[NK];
    float ssum = 0.f, ssq = 0.f;
#pragma unroll
    for (int k = 0; k < NK; k++) {
        ar[k] = 0.f; ai[k] = 0.f;
        int mm = k * lane; if (mm >= HP) mm -= HP;
        m[k] = mm;
        s[k] = (k * 32) % HP;
    }
    for (int it = 0; it < 9; it++) {
        int w = lane + it * 32;
        float xv = (w < HP) ? row[w] : 0.f;
        ssum += xv; ssq += xv * xv;
#pragma unroll
        for (int k = 0; k < NK; k++) {
            float2 t = stw[m[k]];
            ar[k] += xv * t.x;
            ai[k] += xv * t.y;
            m[k] += s[k]; if (m[k] >= HP) m[k] -= HP;
        }
    }
#pragma unroll
    for (int off = 16; off; off >>= 1) {
        ssum += __shfl_xor_sync(0xffffffffu, ssum, off);
        ssq  += __shfl_xor_sync(0xffffffffu, ssq, off);
#pragma unroll
        for (int k = 0; k < NK; k++) {
            ar[k] += __shfl_xor_sync(0xffffffffu, ar[k], off);
            ai[k] += __shfl_xor_sync(0xffffffffu, ai[k], off);
        }
    }
    if (lane == 0) {
        float2* out = g_F + ((size_t)bc * HP + h) * NK;
#pragma unroll
        for (int k = 0; k < NK; k++) out[k] = make_float2(ar[k], ai[k]);
        g_rowstats[(size_t)bc * HP + h] = make_float2(ssum, ssq);
    }
}

// ---------------- deterministic stats reduce (per b,c) ----------------
__global__ void kStats() {
    __shared__ float s1[128], s2[128];
    int bc = blockIdx.x, tid = threadIdx.x;
    float a = 0.f, q = 0.f;
    for (int j = tid; j < HP; j += 128) {
        float2 v = g_rowstats[(size_t)bc * HP + j];
        a += v.x; q += v.y;
    }
    s1[tid] = a; s2[tid] = q;
    __syncthreads();
    for (int off = 64; off; off >>= 1) {
        if (tid < off) { s1[tid] += s1[tid + off]; s2[tid] += s2[tid + off]; }
        __syncthreads();
    }
    if (tid == 0) { g_xsum[bc] = s1[0]; g_xsq[bc] = s2[0]; }
}

// ---------------- stage B: forward DFT along h (265 -> 25) ----------------
__global__ void kB() {
    __shared__ float2 sT[HP * NK];
    __shared__ float2 stw[HP];
    int bc = blockIdx.x, tid = threadIdx.x;
    for (int j = tid; j < HP; j += 256) stw[j] = g_tw[j];
    for (int j = tid; j < HP * NK; j += 256) sT[j] = g_F[(size_t)bc * HP * NK + j];
    __syncthreads();
    for (int out = tid; out < NPOS; out += 256) {
        int y = out / NK, kx = out % NK;
        int kk = (y + 253) % HP;            // ky = y-12 mod 265
        float ar = 0.f, ai = 0.f;
        int mm = 0;
        for (int h = 0; h < HP; h++) {
            float2 T = sT[h * NK + kx];
            float2 t = stw[mm];
            ar += T.x * t.x - T.y * t.y;
            ai += T.x * t.y + T.y * t.x;
            mm += kk; if (mm >= HP) mm -= HP;
        }
        g_S[(size_t)bc * NPOS + out] = make_float2(ar, ai);
    }
}

// ---------------- mode mix: normalize input spectrally, apply Wfull ----------------
__global__ void kM1(int layer) {
    __shared__ float2 sx[32 * 65];
    __shared__ float smu[32], sis[32];
    int b = blockIdx.x, chunk = blockIdx.y, tid = threadIdx.x;
    int p0 = chunk * 65;
    if (tid < 32) {
        float mu = g_xsum[b * 32 + tid] * INV_N;
        float vr = g_xsq[b * 32 + tid] * INV_N - mu * mu;
        smu[tid] = mu;
        sis[tid] = rsqrtf(vr + 1e-5f);
    }
    __syncthreads();
    for (int j = tid; j < 32 * 65; j += 256) {
        int i = j / 65, p = p0 + (j % 65);
        float2 v = g_S[((size_t)b * 32 + i) * NPOS + p];
        float re = v.x;
        if (p == DCPOS) re -= smu[i] * NF;   // subtract mean at DC
        sx[j] = make_float2(re * sis[i], v.y * sis[i]);
    }
    __syncthreads();
    for (int out = tid; out < 65 * 32; out += 256) {
        int o = out & 31, pl = out >> 5;
        int pos = p0 + pl;
        const float* wp = g_Wf + ((size_t)(layer * NPOS + pos) * 32) * 32 + o;
        float ar = 0.f, ai = 0.f;
#pragma unroll
        for (int i = 0; i < 32; i++) {
            float wv = wp[(size_t)i * 32];
            float2 xv = sx[i * 65 + pl];
            ar += wv * xv.x;
            ai += wv * xv.y;
        }
        g_Z[((size_t)b * 32 + o) * NPOS + pos] = make_float2(ar, ai);
    }
}

// ---------------- spectral stats of irfft output (Parseval) ----------------
__global__ void kM2() {
    int bo = blockIdx.x, lane = threadIdx.x;
    const float2* Z = g_Z + (size_t)bo * NPOS;
    double acc = 0.0;
    for (int pos = lane; pos < NPOS; pos += 32) {
        int kx = pos % NK;
        float2 z = Z[pos];
        if (kx == 0) {
            int y = pos / NK;
            float2 z2 = Z[(24 - y) * NK];
            float sr = 0.5f * (z.x + z2.x);
            float si = 0.5f * (z.y - z2.y);
            acc += (double)(sr * sr + si * si);
        } else {
            acc += 2.0 * (double)(z.x * z.x + z.y * z.y);
        }
    }
#pragma unroll
    for (int off = 16; off; off >>= 1)
        acc += __shfl_xor_sync(0xffffffffu, acc, off);
    if (lane == 0) {
        float mean = Z[DCPOS].x * INV_N;
        double var = acc * (double)INV_N * (double)INV_N - (double)mean * (double)mean;
        g_ymu[bo] = mean;
        g_yisig[bo] = rsqrtf((float)var + 1e-5f);
    }
}

// ---------------- stage C: inverse DFT along h (25 -> 265) ----------------
__global__ void kC() {
    __shared__ float2 sZ[NPOS];
    __shared__ float2 stw[HP];
    int bo = blockIdx.x, tid = threadIdx.x;
    for (int j = tid; j < HP; j += 256) stw[j] = g_tw[j];
    for (int j = tid; j < NPOS; j += 256) sZ[j] = g_Z[(size_t)bo * NPOS + j];
    __syncthreads();
    int j = blockIdx.y * 256 + tid;
    if (j >= HP * NK) return;
    int h = j / NK, kx = j % NK;
    int mm = (253 * h) % HP;   // start at ky=-12
    int step = h;
    float ar = 0.f, ai = 0.f;
#pragma unroll
    for (int y = 0; y < NY; y++) {
        float2 z = sZ[y * NK + kx];
        float2 t = stw[mm];   // conj(t) gives e^{+i}
        ar += z.x * t.x + z.y * t.y;
        ai += z.y * t.x - z.x * t.y;
        mm += step; if (mm >= HP) mm -= HP;
    }
    g_F[(size_t)bo * HP * NK + j] = make_float2(ar, ai);
}

// ---------------- stage D (fused): inverse DFT along w + inorm + mlp1/gelu/mlp2 + wconv + residual (+gelu) ----------------
template<int LAYER, bool DOGELU>
__global__ void __launch_bounds__(288) kD(const float* __restrict__ ww, const float* __restrict__ wb) {
    __shared__ float sGr[NK][32], sGi[NK][32], sc0[32];
    __shared__ float sww[32][32];
    __shared__ float swb[32];
    __shared__ float2 stw[HP];
    int h = blockIdx.x, b = blockIdx.y, tid = threadIdx.x;
    for (int j = tid; j < HP; j += 288) stw[j] = g_tw[j];
    for (int j = tid; j < 1024; j += 288) sww[j >> 5][j & 31] = ww[LAYER * 1024 + j];
    if (tid < 32) swb[tid] = wb[LAYER * 32 + tid];
    for (int j = tid; j < 32 * NK; j += 288) {
        int o = j / NK, kx = j % NK;
        float2 G = g_F[(((size_t)b * 32 + o) * HP + h) * NK + kx];
        float mu = g_ymu[b * 32 + o], isig = g_yisig[b * 32 + o];
        if (kx == 0) {
            sc0[o] = G.x * isig * INV_N - mu * isig;
        } else {
            sGr[kx][o] = G.x * (2.f * isig * INV_N);
            sGi[kx][o] = G.y * (2.f * isig * INV_N);
        }
    }
    __syncthreads();
    int w = tid;
    if (w >= HP) return;
    size_t base = (((size_t)b * 32) * HP + h) * HP + w;
    float xin[32];
#pragma unroll
    for (int c = 0; c < 32; c++) xin[c] = g_x[base + (size_t)c * NPIX];
    float cc[NK], ss[NK];
    {
        int m = w;
#pragma unroll
        for (int k = 1; k < NK; k++) {
            cc[k] = stw[m].x; ss[k] = stw[m].y;
            m += w; if (m >= HP) m -= HP;
        }
    }
    float x1n[32];
#pragma unroll
    for (int o = 0; o < 32; o++) x1n[o] = sc0[o];
#pragma unroll
    for (int k = 1; k < NK; k++) {
        float c = cc[k], s = ss[k];
        const float4* gr = (const float4*)sGr[k];
        const float4* gi = (const float4*)sGi[k];
#pragma unroll
        for (int o4 = 0; o4 < 8; o4++) {
            float4 r = gr[o4], im = gi[o4];
            x1n[4 * o4 + 0] += r.x * c + im.x * s;
            x1n[4 * o4 + 1] += r.y * c + im.y * s;
            x1n[4 * o4 + 2] += r.z * c + im.z * s;
            x1n[4 * o4 + 3] += r.w * c + im.w * s;
        }
    }
    float h1[32];
#pragma unroll
    for (int j = 0; j < 32; j++) {
        float v = c_m1b[LAYER * 32 + j];
#pragma unroll
        for (int i4 = 0; i4 < 8; i4++) {
            float4 wv = *(const float4*)&c_m1w[LAYER * 1024 + j * 32 + i4 * 4];
            v += wv.x * x1n[4 * i4] + wv.y * x1n[4 * i4 + 1]
               + wv.z * x1n[4 * i4 + 2] + wv.w * x1n[4 * i4 + 3];
        }
        h1[j] = gelu(v);
    }
#pragma unroll
    for (int o = 0; o < 32; o++) {
        float v = c_m2b[LAYER * 32 + o] + swb[o];
#pragma unroll
        for (int i4 = 0; i4 < 8; i4++) {
            float4 wv = *(const float4*)&c_m2w[LAYER * 1024 + o * 32 + i4 * 4];
            v += wv.x * h1[4 * i4] + wv.y * h1[4 * i4 + 1]
               + wv.z * h1[4 * i4 + 2] + wv.w * h1[4 * i4 + 3];
        }
        const float4* wr = (const float4*)sww[o];
#pragma unroll
        for (int i4 = 0; i4 < 8; i4++) {
            float4 q = wr[i4];
            v += q.x * xin[4 * i4] + q.y * xin[4 * i4 + 1] + q.z * xin[4 * i4 + 2] + q.w * xin[4 * i4 + 3];
        }
        if (DOGELU) v = gelu(v);
        g_x[base + (size_t)o * NPIX] = v;
    }
}

// ---------------- final: crop + q1 + gelu + q2 ----------------
__global__ void __launch_bounds__(256) kFinal(float* __restrict__ out) {
    int idx = blockIdx.x * 256 + threadIdx.x;
    if (idx >= BATCH * 65536) return;
    int w = idx & 255, h = (idx >> 8) & 255, b = idx >> 16;
    size_t base = (((size_t)b * 32) * HP + h) * HP + w;
    float xin[32];
#pragma unroll
    for (int c = 0; c < 32; c++) xin[c] = g_x[base + (size_t)c * NPIX];
    float acc = c_q2b[0];
#pragma unroll
    for (int j = 0; j < 128; j++) {
        float v = c_q1b[j];
#pragma unroll
        for (int i4 = 0; i4 < 8; i4++) {
            float4 wv = *(const float4*)&c_q1w[j * 32 + i4 * 4];
            v += wv.x * xin[4 * i4] + wv.y * xin[4 * i4 + 1]
               + wv.z * xin[4 * i4 + 2] + wv.w * xin[4 * i4 + 3];
        }
        acc += c_q2w[j] * gelu(v);
    }
    out[idx] = acc;
}

// ---------------- host driver ----------------
extern "C" void kernel_launch(void* const* d_in, const int* in_sizes, int n_in,
                              void* d_out, int out_size) {
    const float* x     = (const float*)d_in[0];
    const float* p_w   = (const float*)d_in[1];
    const float* p_b   = (const float*)d_in[2];
    const float* W_LC  = (const float*)d_in[3];
    const float* W_LR  = (const float*)d_in[4];
    const float* m1w   = (const float*)d_in[5];
    const float* m1b   = (const float*)d_in[6];
    const float* m2w   = (const float*)d_in[7];
    const float* m2b   = (const float*)d_in[8];
    const float* w_w   = (const float*)d_in[9];
    const float* w_b   = (const float*)d_in[10];
    const float* q1w   = (const float*)d_in[11];
    const float* q1b   = (const float*)d_in[12];
    const float* q2w   = (const float*)d_in[13];
    const float* q2b   = (const float*)d_in[14];

    cudaMemcpyToSymbolAsync(c_pw,  p_w, 32 * 4,      0, cudaMemcpyDeviceToDevice, 0);
    cudaMemcpyToSymbolAsync(c_pb,  p_b, 32 * 4,      0, cudaMemcpyDeviceToDevice, 0);
    cudaMemcpyToSymbolAsync(c_m1w, m1w, NL * 1024 * 4, 0, cudaMemcpyDeviceToDevice, 0);
    cudaMemcpyToSymbolAsync(c_m1b, m1b, NL * 32 * 4,   0, cudaMemcpyDeviceToDevice, 0);
    cudaMemcpyToSymbolAsync(c_m2w, m2w, NL * 1024 * 4, 0, cudaMemcpyDeviceToDevice, 0);
    cudaMemcpyToSymbolAsync(c_m2b, m2b, NL * 32 * 4,   0, cudaMemcpyDeviceToDevice, 0);
    cudaMemcpyToSymbolAsync(c_q1w, q1w, 128 * 32 * 4,  0, cudaMemcpyDeviceToDevice, 0);
    cudaMemcpyToSymbolAsync(c_q1b, q1b, 128 * 4,       0, cudaMemcpyDeviceToDevice, 0);
    cudaMemcpyToSymbolAsync(c_q2w, q2w, 128 * 4,       0, cudaMemcpyDeviceToDevice, 0);
    cudaMemcpyToSymbolAsync(c_q2b, q2b, 1 * 4,         0, cudaMemcpyDeviceToDevice, 0);

    k_tw<<<1, 288>>>();
    k_buildW<<<(NL * NPOS * 1024 + 255) / 256, 256>>>(W_LC, W_LR);
    k_lift<<<(int)(((size_t)BATCH * CW * NPIX + 255) / 256), 256>>>(x);

    // layer 0
    kA<<<dim3(BATCH * CW, 34), 256>>>();
    kStats<<<BATCH * CW, 128>>>();
    kB<<<BATCH * CW, 256>>>();
    kM1<<<dim3(BATCH, 5), 256>>>(0);
    kM2<<<BATCH * CW, 32>>>();
    kC<<<dim3(BATCH * CW, 14), 256>>>();
    kD<0, true><<<dim3(HP, BATCH), 288>>>(w_w, w_b);
    // layer 1
    kA<<<dim3(BATCH * CW, 34), 256>>>();
    kStats<<<BATCH * CW, 128>>>();
    kB<<<BATCH * CW, 256>>>();
    kM1<<<dim3(BATCH, 5), 256>>>(1);
    kM2<<<BATCH * CW, 32>>>();
    kC<<<dim3(BATCH * CW, 14), 256>>>();
    kD<1, true><<<dim3(HP, BATCH), 288>>>(w_w, w_b);
    // layer 2
    kA<<<dim3(BATCH * CW, 34), 256>>>();
    kStats<<<BATCH * CW, 128>>>();
    kB<<<BATCH * CW, 256>>>();
    kM1<<<dim3(BATCH, 5), 256>>>(2);
    kM2<<<BATCH * CW, 32>>>();
    kC<<<dim3(BATCH * CW, 14), 256>>>();
    kD<2, true><<<dim3(HP, BATCH), 288>>>(w_w, w_b);
    // layer 3 (no trailing gelu)
    kA<<<dim3(BATCH * CW, 34), 256>>>();
    kStats<<<BATCH * CW, 128>>>();
    kB<<<BATCH * CW, 256>>>();
    kM1<<<dim3(BATCH, 5), 256>>>(3);
    kM2<<<BATCH * CW, 32>>>();
    kC<<<dim3(BATCH * CW, 14), 256>>>();
    kD<3, false><<<dim3(HP, BATCH), 288>>>(w_w, w_b);

    kFinal<<<(BATCH * 65536 + 255) / 256, 256>>>((float*)d_out);
}

// round 16
// speedup vs baseline: 1.4557x; 1.4557x over previous
#include <cuda_runtime.h>
#include <math.h>

// ---------------- problem constants ----------------
#define BATCH 16
#define CW    32          // width (channels)
#define HP    265         // padded H = W = 256 + 9
#define NPIX  70225       // 265*265
#define NK    13          // kept kx modes 0..12
#define NY    25          // kept ky modes -12..12
#define NPOS  325         // 25*13
#define NL    4
#define DCPOS 156         // (ky=0 -> y=12)*13 + 0
#define NF    70225.0f
#define INV_N (1.0f/70225.0f)

typedef unsigned long long ull;

// ---------------- packed f32x2 helpers ----------------
__device__ __forceinline__ ull pk(float lo, float hi) {
    ull r; asm("mov.b64 %0, {%1, %2};" : "=l"(r) : "f"(lo), "f"(hi)); return r;
}
__device__ __forceinline__ ull dup2(float v) {
    ull r; asm("mov.b64 %0, {%1, %1};" : "=l"(r) : "f"(v)); return r;
}
__device__ __forceinline__ void upk(ull v, float& lo, float& hi) {
    asm("mov.b64 {%0, %1}, %2;" : "=f"(lo), "=f"(hi) : "l"(v));
}
__device__ __forceinline__ ull fma2(ull a, ull b, ull c) {
    ull d; asm("fma.rn.f32x2 %0, %1, %2, %3;" : "=l"(d) : "l"(a), "l"(b), "l"(c)); return d;
}
__device__ __forceinline__ ull add2(ull a, ull b) {
    ull d; asm("add.rn.f32x2 %0, %1, %2;" : "=l"(d) : "l"(a), "l"(b)); return d;
}

// ---------------- scratch (device globals; no allocation allowed) ----------------
__device__ float  g_x[(size_t)BATCH*CW*NPIX];        // main activation buffer, [b][c][h][w]
__device__ float2 g_F[(size_t)BATCH*CW*HP*NK];       // forward T1 / inverse G, [bc][h][kx]
__device__ float2 g_S[(size_t)BATCH*CW*NPOS];        // extracted modes (raw, pre-norm)
__device__ float2 g_Z[(size_t)BATCH*CW*NPOS];        // mixed modes
__device__ float  g_Wf[(size_t)NL*NPOS*CW*CW];       // built spectral weights, [l][pos][i][o]
__device__ float2 g_tw[HP];                          // e^{-2*pi*i*n/265}
__device__ float2 g_rowstats[(size_t)BATCH*CW*HP];   // per-row (sum, sumsq) of x
__device__ float  g_xsum[BATCH*CW], g_xsq[BATCH*CW];
__device__ float  g_ymu[BATCH*CW], g_yisig[BATCH*CW];

// ---------------- constant weights ----------------
__constant__ float c_pw[32], c_pb[32];
__constant__ __align__(16) float c_m1w[NL*1024];
__constant__ float c_m1b[NL*32];
__constant__ __align__(16) float c_m2w[NL*1024];
__constant__ float c_m2b[NL*32];
__constant__ __align__(16) float c_q1w[128*32];
__constant__ float c_q1b[128];
__constant__ float c_q2w[128], c_q2b[1];

__device__ __forceinline__ float gelu(float v) {
    return 0.5f * v * (1.0f + erff(v * 0.7071067811865476f));
}

// ---------------- twiddle table (double precision init) ----------------
__global__ void k_tw() {
    int n = threadIdx.x;
    if (n < HP) {
        double a = -2.0 * 3.14159265358979323846 * (double)n / 265.0;
        g_tw[n] = make_float2((float)cos(a), (float)sin(a));
    }
}

// ---------------- build Wfull from W_LC / W_LR ----------------
__global__ void k_buildW(const float* __restrict__ LC, const float* __restrict__ LR) {
    int idx = blockIdx.x * blockDim.x + threadIdx.x;
    if (idx >= NL * NPOS * 32 * 32) return;
    int o = idx & 31;
    int i = (idx >> 5) & 31;
    int pos = (idx >> 10) % NPOS;
    int l = idx / (NPOS * 1024);
    int y = pos / 13, x = pos % 13;
    int base = (l * 32 + i) * 32 + o;
    float v;
    if (y < 13) {
        if (x == 0) {
            v = LC[base * 13 + (12 - y)];
        } else {
            int r = x - 1, c = 12 - y;
            v = (c == 0) ? LC[base * 13 + (r + 1)]
                         : LR[(base * 12 + r) * 12 + (c - 1)];
        }
    } else {
        int r = y - 13;
        v = (x == 0) ? LC[base * 13 + (r + 1)]
                     : LR[(base * 12 + r) * 12 + (x - 1)];
    }
    g_Wf[idx] = v;
}

// ---------------- lift: conv1x1 (1->32) + zero pad to 265x265 ----------------
__global__ void k_lift(const float* __restrict__ xin) {
    size_t idx = (size_t)blockIdx.x * blockDim.x + threadIdx.x;
    if (idx >= (size_t)BATCH * CW * NPIX) return;
    int w = (int)(idx % HP);
    int h = (int)((idx / HP) % HP);
    int o = (int)((idx / NPIX) % CW);
    int b = (int)(idx / ((size_t)NPIX * CW));
    float v = 0.f;
    if (h < 256 && w < 256)
        v = c_pw[o] * xin[((size_t)b * 256 + h) * 256 + w] + c_pb[o];
    g_x[idx] = v;
}

// ---------------- stage A: forward DFT along w (265 -> 13), 2 rows/warp, f32x2 ----------------
__global__ void __launch_bounds__(256) kA() {
    __shared__ float2 stw[HP];
    int tid = threadIdx.x;
    for (int j = tid; j < HP; j += 256) stw[j] = g_tw[j];
    __syncthreads();
    int warp = tid >> 5, lane = tid & 31;
    int h0 = blockIdx.y * 16 + warp * 2;
    int bc = blockIdx.x;
    if (h0 >= HP) return;
    bool has1 = (h0 + 1) < HP;
    const float* r0 = g_x + ((size_t)bc * HP + h0) * HP;
    const float* r1 = r0 + (has1 ? HP : 0);
    ull a0[NK], a1[NK];
    int m[NK], s[NK];
#pragma unroll
    for (int k = 0; k < NK; k++) {
        a0[k] = 0ull; a1[k] = 0ull;
        int mm = k * lane; if (mm >= HP) mm -= HP;
        m[k] = mm;
        s[k] = (k * 32) % HP;
    }
    float s0s = 0.f, s0q = 0.f, s1s = 0.f, s1q = 0.f;
    for (int it = 0; it < 9; it++) {
        int w = lane + it * 32;
        float x0 = 0.f, x1 = 0.f;
        if (w < HP) { x0 = r0[w]; x1 = r1[w]; }
        s0s += x0; s0q += x0 * x0;
        s1s += x1; s1q += x1 * x1;
        ull d0 = dup2(x0), d1 = dup2(x1);
#pragma unroll
        for (int k = 0; k < NK; k++) {
            ull t = *(const ull*)&stw[m[k]];
            a0[k] = fma2(t, d0, a0[k]);
            a1[k] = fma2(t, d1, a1[k]);
            m[k] += s[k]; if (m[k] >= HP) m[k] -= HP;
        }
    }
#pragma unroll
    for (int off = 16; off; off >>= 1) {
        s0s += __shfl_xor_sync(0xffffffffu, s0s, off);
        s0q += __shfl_xor_sync(0xffffffffu, s0q, off);
        s1s += __shfl_xor_sync(0xffffffffu, s1s, off);
        s1q += __shfl_xor_sync(0xffffffffu, s1q, off);
#pragma unroll
        for (int k = 0; k < NK; k++) {
            a0[k] = add2(a0[k], __shfl_xor_sync(0xffffffffu, a0[k], off));
            a1[k] = add2(a1[k], __shfl_xor_sync(0xffffffffu, a1[k], off));
        }
    }
    if (lane == 0) {
        ull* out0 = (ull*)(g_F + ((size_t)bc * HP + h0) * NK);
#pragma unroll
        for (int k = 0; k < NK; k++) out0[k] = a0[k];
        g_rowstats[(size_t)bc * HP + h0] = make_float2(s0s, s0q);
        if (has1) {
            ull* out1 = out0 + NK;
#pragma unroll
            for (int k = 0; k < NK; k++) out1[k] = a1[k];
            g_rowstats[(size_t)bc * HP + h0 + 1] = make_float2(s1s, s1q);
        }
    }
}

// ---------------- deterministic stats reduce (per b,c) ----------------
__global__ void kStats() {
    __shared__ float s1[128], s2[128];
    int bc = blockIdx.x, tid = threadIdx.x;
    float a = 0.f, q = 0.f;
    for (int j = tid; j < HP; j += 128) {
        float2 v = g_rowstats[(size_t)bc * HP + j];
        a += v.x; q += v.y;
    }
    s1[tid] = a; s2[tid] = q;
    __syncthreads();
    for (int off = 64; off; off >>= 1) {
        if (tid < off) { s1[tid] += s1[tid + off]; s2[tid] += s2[tid + off]; }
        __syncthreads();
    }
    if (tid == 0) { g_xsum[bc] = s1[0]; g_xsq[bc] = s2[0]; }
}

// ---------------- stage B: forward DFT along h (265 -> 25) ----------------
__global__ void kB() {
    __shared__ float2 sT[HP * NK];
    __shared__ float2 stw[HP];
    int bc = blockIdx.x, tid = threadIdx.x;
    for (int j = tid; j < HP; j += 256) stw[j] = g_tw[j];
    for (int j = tid; j < HP * NK; j += 256) sT[j] = g_F[(size_t)bc * HP * NK + j];
    __syncthreads();
    for (int out = tid; out < NPOS; out += 256) {
        int y = out / NK, kx = out % NK;
        int kk = (y + 253) % HP;            // ky = y-12 mod 265
        float ar = 0.f, ai = 0.f;
        int mm = 0;
        for (int h = 0; h < HP; h++) {
            float2 T = sT[h * NK + kx];
            float2 t = stw[mm];
            ar += T.x * t.x - T.y * t.y;
            ai += T.x * t.y + T.y * t.x;
            mm += kk; if (mm >= HP) mm -= HP;
        }
        g_S[(size_t)bc * NPOS + out] = make_float2(ar, ai);
    }
}

// ---------------- mode mix: normalize input spectrally, apply Wfull ----------------
__global__ void kM1(int layer) {
    __shared__ float2 sx[32 * 65];
    __shared__ float smu[32], sis[32];
    int b = blockIdx.x, chunk = blockIdx.y, tid = threadIdx.x;
    int p0 = chunk * 65;
    if (tid < 32) {
        float mu = g_xsum[b * 32 + tid] * INV_N;
        float vr = g_xsq[b * 32 + tid] * INV_N - mu * mu;
        smu[tid] = mu;
        sis[tid] = rsqrtf(vr + 1e-5f);
    }
    __syncthreads();
    for (int j = tid; j < 32 * 65; j += 256) {
        int i = j / 65, p = p0 + (j % 65);
        float2 v = g_S[((size_t)b * 32 + i) * NPOS + p];
        float re = v.x;
        if (p == DCPOS) re -= smu[i] * NF;   // subtract mean at DC
        sx[j] = make_float2(re * sis[i], v.y * sis[i]);
    }
    __syncthreads();
    for (int out = tid; out < 65 * 32; out += 256) {
        int o = out & 31, pl = out >> 5;
        int pos = p0 + pl;
        const float* wp = g_Wf + ((size_t)(layer * NPOS + pos) * 32) * 32 + o;
        float ar = 0.f, ai = 0.f;
#pragma unroll
        for (int i = 0; i < 32; i++) {
            float wv = wp[(size_t)i * 32];
            float2 xv = sx[i * 65 + pl];
            ar += wv * xv.x;
            ai += wv * xv.y;
        }
        g_Z[((size_t)b * 32 + o) * NPOS + pos] = make_float2(ar, ai);
    }
}

// ---------------- spectral stats of irfft output (Parseval) ----------------
__global__ void kM2() {
    int bo = blockIdx.x, lane = threadIdx.x;
    const float2* Z = g_Z + (size_t)bo * NPOS;
    double acc = 0.0;
    for (int pos = lane; pos < NPOS; pos += 32) {
        int kx = pos % NK;
        float2 z = Z[pos];
        if (kx == 0) {
            int y = pos / NK;
            float2 z2 = Z[(24 - y) * NK];
            float sr = 0.5f * (z.x + z2.x);
            float si = 0.5f * (z.y - z2.y);
            acc += (double)(sr * sr + si * si);
        } else {
            acc += 2.0 * (double)(z.x * z.x + z.y * z.y);
        }
    }
#pragma unroll
    for (int off = 16; off; off >>= 1)
        acc += __shfl_xor_sync(0xffffffffu, acc, off);
    if (lane == 0) {
        float mean = Z[DCPOS].x * INV_N;
        double var = acc * (double)INV_N * (double)INV_N - (double)mean * (double)mean;
        g_ymu[bo] = mean;
        g_yisig[bo] = rsqrtf((float)var + 1e-5f);
    }
}

// ---------------- stage C: inverse DFT along h (25 -> 265) ----------------
__global__ void kC() {
    __shared__ float2 sZ[NPOS];
    __shared__ float2 stw[HP];
    int bo = blockIdx.x, tid = threadIdx.x;
    for (int j = tid; j < HP; j += 256) stw[j] = g_tw[j];
    for (int j = tid; j < NPOS; j += 256) sZ[j] = g_Z[(size_t)bo * NPOS + j];
    __syncthreads();
    int j = blockIdx.y * 256 + tid;
    if (j >= HP * NK) return;
    int h = j / NK, kx = j % NK;
    int mm = (253 * h) % HP;   // start at ky=-12
    int step = h;
    float ar = 0.f, ai = 0.f;
#pragma unroll
    for (int y = 0; y < NY; y++) {
        float2 z = sZ[y * NK + kx];
        float2 t = stw[mm];   // conj(t) gives e^{+i}
        ar += z.x * t.x + z.y * t.y;
        ai += z.y * t.x - z.x * t.y;
        mm += step; if (mm >= HP) mm -= HP;
    }
    g_F[(size_t)bo * HP * NK + j] = make_float2(ar, ai);
}

// ---------------- stage D (fused): idft_w + inorm + mlp1/gelu/mlp2 + wconv + residual (+gelu), f32x2 ----------------
template<int LAYER, bool DOGELU>
__global__ void __launch_bounds__(288) kD(const float* __restrict__ ww, const float* __restrict__ wb) {
    __shared__ __align__(16) float sGr[NK][32];
    __shared__ __align__(16) float sGi[NK][32];
    __shared__ __align__(16) float sc0[32];
    __shared__ __align__(16) float sww[32][32];
    __shared__ float swb[32];
    __shared__ float2 stw[HP];
    int h = blockIdx.x, b = blockIdx.y, tid = threadIdx.x;
    for (int j = tid; j < HP; j += 288) stw[j] = g_tw[j];
    for (int j = tid; j < 1024; j += 288) sww[j >> 5][j & 31] = ww[LAYER * 1024 + j];
    if (tid < 32) swb[tid] = wb[LAYER * 32 + tid];
    for (int j = tid; j < 32 * NK; j += 288) {
        int o = j / NK, kx = j % NK;
        float2 G = g_F[(((size_t)b * 32 + o) * HP + h) * NK + kx];
        float mu = g_ymu[b * 32 + o], isig = g_yisig[b * 32 + o];
        if (kx == 0) {
            sc0[o] = G.x * isig * INV_N - mu * isig;
        } else {
            sGr[kx][o] = G.x * (2.f * isig * INV_N);
            sGi[kx][o] = G.y * (2.f * isig * INV_N);
        }
    }
    __syncthreads();
    int w = tid;
    if (w >= HP) return;
    size_t base = (((size_t)b * 32) * HP + h) * HP + w;
    ull xin2[16];
#pragma unroll
    for (int c2 = 0; c2 < 16; c2++) {
        float lo = g_x[base + (size_t)(2 * c2) * NPIX];
        float hi = g_x[base + (size_t)(2 * c2 + 1) * NPIX];
        xin2[c2] = pk(lo, hi);
    }
    float cc[NK], ss[NK];
    {
        int m = w;
#pragma unroll
        for (int k = 1; k < NK; k++) {
            cc[k] = stw[m].x; ss[k] = stw[m].y;
            m += w; if (m >= HP) m -= HP;
        }
    }
    ull x1n2[16];
    {
        const ull* c0 = (const ull*)sc0;
#pragma unroll
        for (int o2 = 0; o2 < 16; o2++) x1n2[o2] = c0[o2];
    }
#pragma unroll
    for (int k = 1; k < NK; k++) {
        ull cd = dup2(cc[k]), sd = dup2(ss[k]);
        const float4* gr4 = (const float4*)sGr[k];
        const float4* gi4 = (const float4*)sGi[k];
#pragma unroll
        for (int o4 = 0; o4 < 8; o4++) {
            float4 r = gr4[o4], im = gi4[o4];
            x1n2[2 * o4]     = fma2(pk(r.x, r.y), cd, fma2(pk(im.x, im.y), sd, x1n2[2 * o4]));
            x1n2[2 * o4 + 1] = fma2(pk(r.z, r.w), cd, fma2(pk(im.z, im.w), sd, x1n2[2 * o4 + 1]));
        }
    }
    float h1[32];
#pragma unroll
    for (int j = 0; j < 32; j++) {
        ull acc = 0ull;
        const float4* w4 = (const float4*)&c_m1w[LAYER * 1024 + j * 32];
#pragma unroll
        for (int i4 = 0; i4 < 8; i4++) {
            float4 wv = w4[i4];
            acc = fma2(pk(wv.x, wv.y), x1n2[2 * i4], acc);
            acc = fma2(pk(wv.z, wv.w), x1n2[2 * i4 + 1], acc);
        }
        float lo, hi; upk(acc, lo, hi);
        h1[j] = gelu(lo + hi + c_m1b[LAYER * 32 + j]);
    }
    ull h2[16];
#pragma unroll
    for (int i2 = 0; i2 < 16; i2++) h2[i2] = pk(h1[2 * i2], h1[2 * i2 + 1]);
#pragma unroll
    for (int o = 0; o < 32; o++) {
        ull acc = 0ull;
        const float4* w4 = (const float4*)&c_m2w[LAYER * 1024 + o * 32];
        const float4* v4 = (const float4*)sww[o];
#pragma unroll
        for (int i4 = 0; i4 < 8; i4++) {
            float4 wv = w4[i4];
            acc = fma2(pk(wv.x, wv.y), h2[2 * i4], acc);
            acc = fma2(pk(wv.z, wv.w), h2[2 * i4 + 1], acc);
        }
#pragma unroll
        for (int i4 = 0; i4 < 8; i4++) {
            float4 qv = v4[i4];
            acc = fma2(pk(qv.x, qv.y), xin2[2 * i4], acc);
            acc = fma2(pk(qv.z, qv.w), xin2[2 * i4 + 1], acc);
        }
        float lo, hi; upk(acc, lo, hi);
        float v = lo + hi + c_m2b[LAYER * 32 + o] + swb[o];
        if (DOGELU) v = gelu(v);
        g_x[base + (size_t)o * NPIX] = v;
    }
}

// ---------------- final: crop + q1 + gelu + q2, f32x2 ----------------
__global__ void __launch_bounds__(256) kFinal(float* __restrict__ out) {
    int idx = blockIdx.x * 256 + threadIdx.x;
    if (idx >= BATCH * 65536) return;
    int w = idx & 255, h = (idx >> 8) & 255, b = idx >> 16;
    size_t base = (((size_t)b * 32) * HP + h) * HP + w;
    ull xin2[16];
#pragma unroll
    for (int c2 = 0; c2 < 16; c2++) {
        float lo = g_x[base + (size_t)(2 * c2) * NPIX];
        float hi = g_x[base + (size_t)(2 * c2 + 1) * NPIX];
        xin2[c2] = pk(lo, hi);
    }
    float acc = c_q2b[0];
#pragma unroll
    for (int j = 0; j < 128; j++) {
        ull a2 = 0ull;
        const float4* w4 = (const float4*)&c_q1w[j * 32];
#pragma unroll
        for (int i4 = 0; i4 < 8; i4++) {
            float4 wv = w4[i4];
            a2 = fma2(pk(wv.x, wv.y), xin2[2 * i4], a2);
            a2 = fma2(pk(wv.z, wv.w), xin2[2 * i4 + 1], a2);
        }
        float lo, hi; upk(a2, lo, hi);
        acc += c_q2w[j] * gelu(lo + hi + c_q1b[j]);
    }
    out[idx] = acc;
}

// ---------------- host driver ----------------
extern "C" void kernel_launch(void* const* d_in, const int* in_sizes, int n_in,
                              void* d_out, int out_size) {
    const float* x     = (const float*)d_in[0];
    const float* p_w   = (const float*)d_in[1];
    const float* p_b   = (const float*)d_in[2];
    const float* W_LC  = (const float*)d_in[3];
    const float* W_LR  = (const float*)d_in[4];
    const float* m1w   = (const float*)d_in[5];
    const float* m1b   = (const float*)d_in[6];
    const float* m2w   = (const float*)d_in[7];
    const float* m2b   = (const float*)d_in[8];
    const float* w_w   = (const float*)d_in[9];
    const float* w_b   = (const float*)d_in[10];
    const float* q1w   = (const float*)d_in[11];
    const float* q1b   = (const float*)d_in[12];
    const float* q2w   = (const float*)d_in[13];
    const float* q2b   = (const float*)d_in[14];

    cudaMemcpyToSymbolAsync(c_pw,  p_w, 32 * 4,      0, cudaMemcpyDeviceToDevice, 0);
    cudaMemcpyToSymbolAsync(c_pb,  p_b, 32 * 4,      0, cudaMemcpyDeviceToDevice, 0);
    cudaMemcpyToSymbolAsync(c_m1w, m1w, NL * 1024 * 4, 0, cudaMemcpyDeviceToDevice, 0);
    cudaMemcpyToSymbolAsync(c_m1b, m1b, NL * 32 * 4,   0, cudaMemcpyDeviceToDevice, 0);
    cudaMemcpyToSymbolAsync(c_m2w, m2w, NL * 1024 * 4, 0, cudaMemcpyDeviceToDevice, 0);
    cudaMemcpyToSymbolAsync(c_m2b, m2b, NL * 32 * 4,   0, cudaMemcpyDeviceToDevice, 0);
    cudaMemcpyToSymbolAsync(c_q1w, q1w, 128 * 32 * 4,  0, cudaMemcpyDeviceToDevice, 0);
    cudaMemcpyToSymbolAsync(c_q1b, q1b, 128 * 4,       0, cudaMemcpyDeviceToDevice, 0);
    cudaMemcpyToSymbolAsync(c_q2w, q2w, 128 * 4,       0, cudaMemcpyDeviceToDevice, 0);
    cudaMemcpyToSymbolAsync(c_q2b, q2b, 1 * 4,         0, cudaMemcpyDeviceToDevice, 0);

    k_tw<<<1, 288>>>();
    k_buildW<<<(NL * NPOS * 1024 + 255) / 256, 256>>>(W_LC, W_LR);
    k_lift<<<(int)(((size_t)BATCH * CW * NPIX + 255) / 256), 256>>>(x);

    // layer 0
    kA<<<dim3(BATCH * CW, 17), 256>>>();
    kStats<<<BATCH * CW, 128>>>();
    kB<<<BATCH * CW, 256>>>();
    kM1<<<dim3(BATCH, 5), 256>>>(0);
    kM2<<<BATCH * CW, 32>>>();
    kC<<<dim3(BATCH * CW, 14), 256>>>();
    kD<0, true><<<dim3(HP, BATCH), 288>>>(w_w, w_b);
    // layer 1
    kA<<<dim3(BATCH * CW, 17), 256>>>();
    kStats<<<BATCH * CW, 128>>>();
    kB<<<BATCH * CW, 256>>>();
    kM1<<<dim3(BATCH, 5), 256>>>(1);
    kM2<<<BATCH * CW, 32>>>();
    kC<<<dim3(BATCH * CW, 14), 256>>>();
    kD<1, true><<<dim3(HP, BATCH), 288>>>(w_w, w_b);
    // layer 2
    kA<<<dim3(BATCH * CW, 17), 256>>>();
    kStats<<<BATCH * CW, 128>>>();
    kB<<<BATCH * CW, 256>>>();
    kM1<<<dim3(BATCH, 5), 256>>>(2);
    kM2<<<BATCH * CW, 32>>>();
    kC<<<dim3(BATCH * CW, 14), 256>>>();
    kD<2, true><<<dim3(HP, BATCH), 288>>>(w_w, w_b);
    // layer 3 (no trailing gelu)
    kA<<<dim3(BATCH * CW, 17), 256>>>();
    kStats<<<BATCH * CW, 128>>>();
    kB<<<BATCH * CW, 256>>>();
    kM1<<<dim3(BATCH, 5), 256>>>(3);
    kM2<<<BATCH * CW, 32>>>();
    kC<<<dim3(BATCH * CW, 14), 256>>>();
    kD<3, false><<<dim3(HP, BATCH), 288>>>(w_w, w_b);

    kFinal<<<(BATCH * 65536 + 255) / 256, 256>>>((float*)d_out);
}

// round 17
// speedup vs baseline: 1.6414x; 1.1276x over previous
#include <cuda_runtime.h>
#include <math.h>

// ---------------- problem constants ----------------
#define BATCH 16
#define CW    32          // width (channels)
#define HP    265         // padded H = W = 256 + 9
#define NPIX  70225       // 265*265
#define NK    13          // kept kx modes 0..12
#define NY    25          // kept ky modes -12..12
#define NPOS  325         // 25*13
#define NL    4
#define DCPOS 156         // (ky=0 -> y=12)*13 + 0
#define NF    70225.0f
#define INV_N (1.0f/70225.0f)

typedef unsigned long long ull;

// ---------------- packed f32x2 helpers ----------------
__device__ __forceinline__ ull pk(float lo, float hi) {
    ull r; asm("mov.b64 %0, {%1, %2};" : "=l"(r) : "f"(lo), "f"(hi)); return r;
}
__device__ __forceinline__ ull dup2(float v) {
    ull r; asm("mov.b64 %0, {%1, %1};" : "=l"(r) : "f"(v)); return r;
}
__device__ __forceinline__ void upk(ull v, float& lo, float& hi) {
    asm("mov.b64 {%0, %1}, %2;" : "=f"(lo), "=f"(hi) : "l"(v));
}
__device__ __forceinline__ ull fma2(ull a, ull b, ull c) {
    ull d; asm("fma.rn.f32x2 %0, %1, %2, %3;" : "=l"(d) : "l"(a), "l"(b), "l"(c)); return d;
}
__device__ __forceinline__ ull add2(ull a, ull b) {
    ull d; asm("add.rn.f32x2 %0, %1, %2;" : "=l"(d) : "l"(a), "l"(b)); return d;
}

// ---------------- scratch (device globals; no allocation allowed) ----------------
__device__ float  g_x[(size_t)BATCH*CW*NPIX];        // main activation buffer, [b][c][h][w]
__device__ float2 g_F[(size_t)BATCH*CW*HP*NK];       // forward T1 / inverse G, [bc][h][kx]
__device__ float2 g_S[(size_t)BATCH*CW*NPOS];        // extracted modes (raw, pre-norm)
__device__ float2 g_Z[(size_t)BATCH*CW*NPOS];        // mixed modes
__device__ float  g_Wf[(size_t)NL*NPOS*CW*CW];       // built spectral weights, [l][pos][i][o]
__device__ float2 g_tw[HP];                          // e^{-2*pi*i*n/265}
__device__ float2 g_rowstats[(size_t)BATCH*CW*HP];   // per-row (sum, sumsq) of x
__device__ float  g_xsum[BATCH*CW], g_xsq[BATCH*CW];
__device__ float  g_ymu[BATCH*CW], g_yisig[BATCH*CW];

// ---------------- constant weights ----------------
__constant__ float c_pw[32], c_pb[32];
__constant__ __align__(16) float c_m1w[NL*1024];
__constant__ float c_m1b[NL*32];
__constant__ __align__(16) float c_m2w[NL*1024];
__constant__ float c_m2b[NL*32];
__constant__ __align__(16) float c_q1w[128*32];
__constant__ float c_q1b[128];
__constant__ float c_q2w[128], c_q2b[1];

__device__ __forceinline__ float gelu(float v) {
    return 0.5f * v * (1.0f + erff(v * 0.7071067811865476f));
}

// ---------------- twiddle table (double precision init) ----------------
__global__ void k_tw() {
    int n = threadIdx.x;
    if (n < HP) {
        double a = -2.0 * 3.14159265358979323846 * (double)n / 265.0;
        g_tw[n] = make_float2((float)cos(a), (float)sin(a));
    }
}

// ---------------- build Wfull from W_LC / W_LR ----------------
__global__ void k_buildW(const float* __restrict__ LC, const float* __restrict__ LR) {
    int idx = blockIdx.x * blockDim.x + threadIdx.x;
    if (idx >= NL * NPOS * 32 * 32) return;
    int o = idx & 31;
    int i = (idx >> 5) & 31;
    int pos = (idx >> 10) % NPOS;
    int l = idx / (NPOS * 1024);
    int y = pos / 13, x = pos % 13;
    int base = (l * 32 + i) * 32 + o;
    float v;
    if (y < 13) {
        if (x == 0) {
            v = LC[base * 13 + (12 - y)];
        } else {
            int r = x - 1, c = 12 - y;
            v = (c == 0) ? LC[base * 13 + (r + 1)]
                         : LR[(base * 12 + r) * 12 + (c - 1)];
        }
    } else {
        int r = y - 13;
        v = (x == 0) ? LC[base * 13 + (r + 1)]
                     : LR[(base * 12 + r) * 12 + (x - 1)];
    }
    g_Wf[idx] = v;
}

// ---------------- lift: conv1x1 (1->32) + zero pad to 265x265 ----------------
__global__ void k_lift(const float* __restrict__ xin) {
    size_t idx = (size_t)blockIdx.x * blockDim.x + threadIdx.x;
    if (idx >= (size_t)BATCH * CW * NPIX) return;
    int w = (int)(idx % HP);
    int h = (int)((idx / HP) % HP);
    int o = (int)((idx / NPIX) % CW);
    int b = (int)(idx / ((size_t)NPIX * CW));
    float v = 0.f;
    if (h < 256 && w < 256)
        v = c_pw[o] * xin[((size_t)b * 256 + h) * 256 + w] + c_pb[o];
    g_x[idx] = v;
}

// ---------------- stage A: forward DFT along w (265 -> 13), 2 rows/warp ----------------
// Twiddles generated by per-lane complex recurrence t_k = b^k (b = tw[w]);
// zero shared-memory gathers in the inner loop (old version was L1-conflict-bound).
__global__ void __launch_bounds__(256) kA() {
    __shared__ float2 stw[HP];
    int tid = threadIdx.x;
    for (int j = tid; j < HP; j += 256) stw[j] = g_tw[j];
    __syncthreads();
    int warp = tid >> 5, lane = tid & 31;
    int h0 = blockIdx.y * 16 + warp * 2;
    int bc = blockIdx.x;
    if (h0 >= HP) return;
    bool has1 = (h0 + 1) < HP;
    const float* r0 = g_x + ((size_t)bc * HP + h0) * HP;
    const float* r1 = r0 + (has1 ? HP : 0);
    ull a0[NK], a1[NK];
#pragma unroll
    for (int k = 0; k < NK; k++) { a0[k] = 0ull; a1[k] = 0ull; }
    float s0s = 0.f, s0q = 0.f, s1s = 0.f, s1q = 0.f;
    for (int it = 0; it < 9; it++) {
        int w = lane + it * 32;
        float x0 = 0.f, x1 = 0.f, bcv = 1.f, bsv = 0.f;
        if (w < HP) {
            x0 = r0[w]; x1 = r1[w];
            float2 bb = stw[w];            // conflict-free: consecutive lanes, consecutive words
            bcv = bb.x; bsv = bb.y;
        }
        s0s += x0; s0q += x0 * x0;
        s1s += x1; s1q += x1 * x1;
        ull d0 = dup2(x0), d1 = dup2(x1);
        float tr = 1.f, ti = 0.f;          // t_0 = 1
#pragma unroll
        for (int k = 0; k < NK; k++) {
            ull tp = pk(tr, ti);
            a0[k] = fma2(tp, d0, a0[k]);
            a1[k] = fma2(tp, d1, a1[k]);
            float ntr = fmaf(-ti, bsv, tr * bcv);   // t *= b
            float nti = fmaf(tr, bsv, ti * bcv);
            tr = ntr; ti = nti;
        }
    }
#pragma unroll
    for (int off = 16; off; off >>= 1) {
        s0s += __shfl_xor_sync(0xffffffffu, s0s, off);
        s0q += __shfl_xor_sync(0xffffffffu, s0q, off);
        s1s += __shfl_xor_sync(0xffffffffu, s1s, off);
        s1q += __shfl_xor_sync(0xffffffffu, s1q, off);
#pragma unroll
        for (int k = 0; k < NK; k++) {
            a0[k] = add2(a0[k], __shfl_xor_sync(0xffffffffu, a0[k], off));
            a1[k] = add2(a1[k], __shfl_xor_sync(0xffffffffu, a1[k], off));
        }
    }
    if (lane == 0) {
        ull* out0 = (ull*)(g_F + ((size_t)bc * HP + h0) * NK);
#pragma unroll
        for (int k = 0; k < NK; k++) out0[k] = a0[k];
        g_rowstats[(size_t)bc * HP + h0] = make_float2(s0s, s0q);
        if (has1) {
            ull* out1 = out0 + NK;
#pragma unroll
            for (int k = 0; k < NK; k++) out1[k] = a1[k];
            g_rowstats[(size_t)bc * HP + h0 + 1] = make_float2(s1s, s1q);
        }
    }
}

// ---------------- deterministic stats reduce (per b,c) ----------------
__global__ void kStats() {
    __shared__ float s1[128], s2[128];
    int bc = blockIdx.x, tid = threadIdx.x;
    float a = 0.f, q = 0.f;
    for (int j = tid; j < HP; j += 128) {
        float2 v = g_rowstats[(size_t)bc * HP + j];
        a += v.x; q += v.y;
    }
    s1[tid] = a; s2[tid] = q;
    __syncthreads();
    for (int off = 64; off; off >>= 1) {
        if (tid < off) { s1[tid] += s1[tid + off]; s2[tid] += s2[tid + off]; }
        __syncthreads();
    }
    if (tid == 0) { g_xsum[bc] = s1[0]; g_xsq[bc] = s2[0]; }
}

// ---------------- stage B: forward DFT along h (265 -> 25), recurrence twiddles ----------------
__global__ void kB() {
    __shared__ float2 sT[HP * NK];
    __shared__ float2 stw[HP];
    int bc = blockIdx.x, tid = threadIdx.x;
    for (int j = tid; j < HP; j += 256) stw[j] = g_tw[j];
    for (int j = tid; j < HP * NK; j += 256) sT[j] = g_F[(size_t)bc * HP * NK + j];
    __syncthreads();
    for (int out = tid; out < NPOS; out += 256) {
        int y = out / NK, kx = out % NK;
        int kk = (y + 253) % HP;            // ky = y-12 mod 265
        float2 st = stw[kk];                // constant step; t_h = st^h
        float tr = 1.f, ti = 0.f;
        float ar = 0.f, ai = 0.f;
        for (int h = 0; h < HP; h++) {
            float2 T = sT[h * NK + kx];
            ar = fmaf(T.x, tr, fmaf(-T.y, ti, ar));
            ai = fmaf(T.x, ti, fmaf(T.y, tr, ai));
            float ntr = fmaf(-ti, st.y, tr * st.x);
            float nti = fmaf(tr, st.y, ti * st.x);
            tr = ntr; ti = nti;
        }
        g_S[(size_t)bc * NPOS + out] = make_float2(ar, ai);
    }
}

// ---------------- mode mix: normalize input spectrally, apply Wfull ----------------
__global__ void kM1(int layer) {
    __shared__ float2 sx[32 * 65];
    __shared__ float smu[32], sis[32];
    int b = blockIdx.x, chunk = blockIdx.y, tid = threadIdx.x;
    int p0 = chunk * 65;
    if (tid < 32) {
        float mu = g_xsum[b * 32 + tid] * INV_N;
        float vr = g_xsq[b * 32 + tid] * INV_N - mu * mu;
        smu[tid] = mu;
        sis[tid] = rsqrtf(vr + 1e-5f);
    }
    __syncthreads();
    for (int j = tid; j < 32 * 65; j += 256) {
        int i = j / 65, p = p0 + (j % 65);
        float2 v = g_S[((size_t)b * 32 + i) * NPOS + p];
        float re = v.x;
        if (p == DCPOS) re -= smu[i] * NF;   // subtract mean at DC
        sx[j] = make_float2(re * sis[i], v.y * sis[i]);
    }
    __syncthreads();
    for (int out = tid; out < 65 * 32; out += 256) {
        int o = out & 31, pl = out >> 5;
        int pos = p0 + pl;
        const float* wp = g_Wf + ((size_t)(layer * NPOS + pos) * 32) * 32 + o;
        float ar = 0.f, ai = 0.f;
#pragma unroll
        for (int i = 0; i < 32; i++) {
            float wv = wp[(size_t)i * 32];
            float2 xv = sx[i * 65 + pl];
            ar += wv * xv.x;
            ai += wv * xv.y;
        }
        g_Z[((size_t)b * 32 + o) * NPOS + pos] = make_float2(ar, ai);
    }
}

// ---------------- spectral stats of irfft output (Parseval) ----------------
__global__ void kM2() {
    int bo = blockIdx.x, lane = threadIdx.x;
    const float2* Z = g_Z + (size_t)bo * NPOS;
    double acc = 0.0;
    for (int pos = lane; pos < NPOS; pos += 32) {
        int kx = pos % NK;
        float2 z = Z[pos];
        if (kx == 0) {
            int y = pos / NK;
            float2 z2 = Z[(24 - y) * NK];
            float sr = 0.5f * (z.x + z2.x);
            float si = 0.5f * (z.y - z2.y);
            acc += (double)(sr * sr + si * si);
        } else {
            acc += 2.0 * (double)(z.x * z.x + z.y * z.y);
        }
    }
#pragma unroll
    for (int off = 16; off; off >>= 1)
        acc += __shfl_xor_sync(0xffffffffu, acc, off);
    if (lane == 0) {
        float mean = Z[DCPOS].x * INV_N;
        double var = acc * (double)INV_N * (double)INV_N - (double)mean * (double)mean;
        g_ymu[bo] = mean;
        g_yisig[bo] = rsqrtf((float)var + 1e-5f);
    }
}

// ---------------- stage C: inverse DFT along h (25 -> 265), recurrence twiddles ----------------
__global__ void kC() {
    __shared__ float2 sZ[NPOS];
    __shared__ float2 stw[HP];
    int bo = blockIdx.x, tid = threadIdx.x;
    for (int j = tid; j < HP; j += 256) stw[j] = g_tw[j];
    for (int j = tid; j < NPOS; j += 256) sZ[j] = g_Z[(size_t)bo * NPOS + j];
    __syncthreads();
    int j = blockIdx.y * 256 + tid;
    if (j >= HP * NK) return;
    int h = j / NK, kx = j % NK;
    int m0 = (253 * h) % HP;   // start at ky=-12
    float2 t0 = stw[m0];
    float2 st = stw[h];        // constant step
    float tr = t0.x, ti = t0.y;
    float ar = 0.f, ai = 0.f;
#pragma unroll
    for (int y = 0; y < NY; y++) {
        float2 z = sZ[y * NK + kx];
        // uses conj(t): ar += z.x*tr + z.y*ti; ai += z.y*tr - z.x*ti;
        ar = fmaf(z.x, tr, fmaf(z.y, ti, ar));
        ai = fmaf(z.y, tr, fmaf(-z.x, ti, ai));
        float ntr = fmaf(-ti, st.y, tr * st.x);
        float nti = fmaf(tr, st.y, ti * st.x);
        tr = ntr; ti = nti;
    }
    g_F[(size_t)bo * HP * NK + j] = make_float2(ar, ai);
}

// ---------------- stage D (fused): idft_w + inorm + mlp1/gelu/mlp2 + wconv + residual (+gelu), f32x2 ----------------
template<int LAYER, bool DOGELU>
__global__ void __launch_bounds__(288) kD(const float* __restrict__ ww, const float* __restrict__ wb) {
    __shared__ __align__(16) float sGr[NK][32];
    __shared__ __align__(16) float sGi[NK][32];
    __shared__ __align__(16) float sc0[32];
    __shared__ __align__(16) float sww[32][32];
    __shared__ float swb[32];
    __shared__ float2 stw[HP];
    int h = blockIdx.x, b = blockIdx.y, tid = threadIdx.x;
    for (int j = tid; j < HP; j += 288) stw[j] = g_tw[j];
    for (int j = tid; j < 1024; j += 288) sww[j >> 5][j & 31] = ww[LAYER * 1024 + j];
    if (tid < 32) swb[tid] = wb[LAYER * 32 + tid];
    for (int j = tid; j < 32 * NK; j += 288) {
        int o = j / NK, kx = j % NK;
        float2 G = g_F[(((size_t)b * 32 + o) * HP + h) * NK + kx];
        float mu = g_ymu[b * 32 + o], isig = g_yisig[b * 32 + o];
        if (kx == 0) {
            sc0[o] = G.x * isig * INV_N - mu * isig;
        } else {
            sGr[kx][o] = G.x * (2.f * isig * INV_N);
            sGi[kx][o] = G.y * (2.f * isig * INV_N);
        }
    }
    __syncthreads();
    int w = tid;
    if (w >= HP) return;
    size_t base = (((size_t)b * 32) * HP + h) * HP + w;
    ull xin2[16];
#pragma unroll
    for (int c2 = 0; c2 < 16; c2++) {
        float lo = g_x[base + (size_t)(2 * c2) * NPIX];
        float hi = g_x[base + (size_t)(2 * c2 + 1) * NPIX];
        xin2[c2] = pk(lo, hi);
    }
    float cc[NK], ss[NK];
    {
        int m = w;
#pragma unroll
        for (int k = 1; k < NK; k++) {
            cc[k] = stw[m].x; ss[k] = stw[m].y;
            m += w; if (m >= HP) m -= HP;
        }
    }
    ull x1n2[16];
    {
        const ull* c0 = (const ull*)sc0;
#pragma unroll
        for (int o2 = 0; o2 < 16; o2++) x1n2[o2] = c0[o2];
    }
#pragma unroll
    for (int k = 1; k < NK; k++) {
        ull cd = dup2(cc[k]), sd = dup2(ss[k]);
        const float4* gr4 = (const float4*)sGr[k];
        const float4* gi4 = (const float4*)sGi[k];
#pragma unroll
        for (int o4 = 0; o4 < 8; o4++) {
            float4 r = gr4[o4], im = gi4[o4];
            x1n2[2 * o4]     = fma2(pk(r.x, r.y), cd, fma2(pk(im.x, im.y), sd, x1n2[2 * o4]));
            x1n2[2 * o4 + 1] = fma2(pk(r.z, r.w), cd, fma2(pk(im.z, im.w), sd, x1n2[2 * o4 + 1]));
        }
    }
    float h1[32];
#pragma unroll
    for (int j = 0; j < 32; j++) {
        ull acc = 0ull;
        const float4* w4 = (const float4*)&c_m1w[LAYER * 1024 + j * 32];
#pragma unroll
        for (int i4 = 0; i4 < 8; i4++) {
            float4 wv = w4[i4];
            acc = fma2(pk(wv.x, wv.y), x1n2[2 * i4], acc);
            acc = fma2(pk(wv.z, wv.w), x1n2[2 * i4 + 1], acc);
        }
        float lo, hi; upk(acc, lo, hi);
        h1[j] = gelu(lo + hi + c_m1b[LAYER * 32 + j]);
    }
    ull h2[16];
#pragma unroll
    for (int i2 = 0; i2 < 16; i2++) h2[i2] = pk(h1[2 * i2], h1[2 * i2 + 1]);
#pragma unroll
    for (int o = 0; o < 32; o++) {
        ull acc = 0ull;
        const float4* w4 = (const float4*)&c_m2w[LAYER * 1024 + o * 32];
        const float4* v4 = (const float4*)sww[o];
#pragma unroll
        for (int i4 = 0; i4 < 8; i4++) {
            float4 wv = w4[i4];
            acc = fma2(pk(wv.x, wv.y), h2[2 * i4], acc);
            acc = fma2(pk(wv.z, wv.w), h2[2 * i4 + 1], acc);
        }
#pragma unroll
        for (int i4 = 0; i4 < 8; i4++) {
            float4 qv = v4[i4];
            acc = fma2(pk(qv.x, qv.y), xin2[2 * i4], acc);
            acc = fma2(pk(qv.z, qv.w), xin2[2 * i4 + 1], acc);
        }
        float lo, hi; upk(acc, lo, hi);
        float v = lo + hi + c_m2b[LAYER * 32 + o] + swb[o];
        if (DOGELU) v = gelu(v);
        g_x[base + (size_t)o * NPIX] = v;
    }
}

// ---------------- final: crop + q1 + gelu + q2, f32x2 ----------------
__global__ void __launch_bounds__(256) kFinal(float* __restrict__ out) {
    int idx = blockIdx.x * 256 + threadIdx.x;
    if (idx >= BATCH * 65536) return;
    int w = idx & 255, h = (idx >> 8) & 255, b = idx >> 16;
    size_t base = (((size_t)b * 32) * HP + h) * HP + w;
    ull xin2[16];
#pragma unroll
    for (int c2 = 0; c2 < 16; c2++) {
        float lo = g_x[base + (size_t)(2 * c2) * NPIX];
        float hi = g_x[base + (size_t)(2 * c2 + 1) * NPIX];
        xin2[c2] = pk(lo, hi);
    }
    float acc = c_q2b[0];
#pragma unroll
    for (int j = 0; j < 128; j++) {
        ull a2 = 0ull;
        const float4* w4 = (const float4*)&c_q1w[j * 32];
#pragma unroll
        for (int i4 = 0; i4 < 8; i4++) {
            float4 wv = w4[i4];
            a2 = fma2(pk(wv.x, wv.y), xin2[2 * i4], a2);
            a2 = fma2(pk(wv.z, wv.w), xin2[2 * i4 + 1], a2);
        }
        float lo, hi; upk(a2, lo, hi);
        acc += c_q2w[j] * gelu(lo + hi + c_q1b[j]);
    }
    out[idx] = acc;
}

// ---------------- host driver ----------------
extern "C" void kernel_launch(void* const* d_in, const int* in_sizes, int n_in,
                              void* d_out, int out_size) {
    const float* x     = (const float*)d_in[0];
    const float* p_w   = (const float*)d_in[1];
    const float* p_b   = (const float*)d_in[2];
    const float* W_LC  = (const float*)d_in[3];
    const float* W_LR  = (const float*)d_in[4];
    const float* m1w   = (const float*)d_in[5];
    const float* m1b   = (const float*)d_in[6];
    const float* m2w   = (const float*)d_in[7];
    const float* m2b   = (const float*)d_in[8];
    const float* w_w   = (const float*)d_in[9];
    const float* w_b   = (const float*)d_in[10];
    const float* q1w   = (const float*)d_in[11];
    const float* q1b   = (const float*)d_in[12];
    const float* q2w   = (const float*)d_in[13];
    const float* q2b   = (const float*)d_in[14];

    cudaMemcpyToSymbolAsync(c_pw,  p_w, 32 * 4,      0, cudaMemcpyDeviceToDevice, 0);
    cudaMemcpyToSymbolAsync(c_pb,  p_b, 32 * 4,      0, cudaMemcpyDeviceToDevice, 0);
    cudaMemcpyToSymbolAsync(c_m1w, m1w, NL * 1024 * 4, 0, cudaMemcpyDeviceToDevice, 0);
    cudaMemcpyToSymbolAsync(c_m1b, m1b, NL * 32 * 4,   0, cudaMemcpyDeviceToDevice, 0);
    cudaMemcpyToSymbolAsync(c_m2w, m2w, NL * 1024 * 4, 0, cudaMemcpyDeviceToDevice, 0);
    cudaMemcpyToSymbolAsync(c_m2b, m2b, NL * 32 * 4,   0, cudaMemcpyDeviceToDevice, 0);
    cudaMemcpyToSymbolAsync(c_q1w, q1w, 128 * 32 * 4,  0, cudaMemcpyDeviceToDevice, 0);
    cudaMemcpyToSymbolAsync(c_q1b, q1b, 128 * 4,       0, cudaMemcpyDeviceToDevice, 0);
    cudaMemcpyToSymbolAsync(c_q2w, q2w, 128 * 4,       0, cudaMemcpyDeviceToDevice, 0);
    cudaMemcpyToSymbolAsync(c_q2b, q2b, 1 * 4,         0, cudaMemcpyDeviceToDevice, 0);

    k_tw<<<1, 288>>>();
    k_buildW<<<(NL * NPOS * 1024 + 255) / 256, 256>>>(W_LC, W_LR);
    k_lift<<<(int)(((size_t)BATCH * CW * NPIX + 255) / 256), 256>>>(x);

    // layer 0
    kA<<<dim3(BATCH * CW, 17), 256>>>();
    kStats<<<BATCH * CW, 128>>>();
    kB<<<BATCH * CW, 256>>>();
    kM1<<<dim3(BATCH, 5), 256>>>(0);
    kM2<<<BATCH * CW, 32>>>();
    kC<<<dim3(BATCH * CW, 14), 256>>>();
    kD<0, true><<<dim3(HP, BATCH), 288>>>(w_w, w_b);
    // layer 1
    kA<<<dim3(BATCH * CW, 17), 256>>>();
    kStats<<<BATCH * CW, 128>>>();
    kB<<<BATCH * CW, 256>>>();
    kM1<<<dim3(BATCH, 5), 256>>>(1);
    kM2<<<BATCH * CW, 32>>>();
    kC<<<dim3(BATCH * CW, 14), 256>>>();
    kD<1, true><<<dim3(HP, BATCH), 288>>>(w_w, w_b);
    // layer 2
    kA<<<dim3(BATCH * CW, 17), 256>>>();
    kStats<<<BATCH * CW, 128>>>();
    kB<<<BATCH * CW, 256>>>();
    kM1<<<dim3(BATCH, 5), 256>>>(2);
    kM2<<<BATCH * CW, 32>>>();
    kC<<<dim3(BATCH * CW, 14), 256>>>();
    kD<2, true><<<dim3(HP, BATCH), 288>>>(w_w, w_b);
    // layer 3 (no trailing gelu)
    kA<<<dim3(BATCH * CW, 17), 256>>>();
    kStats<<<BATCH * CW, 128>>>();
    kB<<<BATCH * CW, 256>>>();
    kM1<<<dim3(BATCH, 5), 256>>>(3);
    kM2<<<BATCH * CW, 32>>>();
    kC<<<dim3(BATCH * CW, 14), 256>>>();
    kD<3, false><<<dim3(HP, BATCH), 288>>>(w_w, w_b);

    kFinal<<<(BATCH * 65536 + 255) / 256, 256>>>((float*)d_out);
}